// round 4
// baseline (speedup 1.0000x reference)
#include <cuda_runtime.h>
#include <cuda_bf16.h>

// ShiftLayer: out[b,t,c] = in[b, t+off[c], c], off[c] = {0,-1,+1} for c%3 = {0,1,2},
// zero padding at sequence ends. B=8, L=8192, C=384, fp32.
//
// Warp per (batch, 32-row chunk, 128-channel group). Lane owns the float4 at
// channel 4*lane+128*g. Rows stream through registers, processed in batches of
// 4: four independent LDG.128 issued back-to-back (MLP=4), then four STG.128.
// Fully coalesced 512B warp transactions, no shared memory, no barriers.

#define B_DIM 8
#define L_DIM 8192
#define C_DIM 384
#define T_R   32                        // rows per warp chunk
#define GROUPS 3                        // 128-channel column groups
#define WARPS_PER_BLOCK 4
#define THREADS (WARPS_PER_BLOCK * 32)

__device__ __forceinline__ float4 ldg4(const float* p) {
    return *reinterpret_cast<const float4*>(p);
}
__device__ __forceinline__ void stg4(float* p, float4 v) {
    *reinterpret_cast<float4*>(p) = v;
}

// Component j of this lane's float4 has channel residue (m + j) % 3.
// residue 0 -> cur, 1 -> prev (out[t]=in[t-1]), 2 -> next (out[t]=in[t+1]).
__device__ __forceinline__ float4 route(float4 p, float4 c, float4 n,
                                        bool is1, bool is2) {
    float4 o;
    o.x = is1 ? p.x : (is2 ? n.x : c.x);   // residue m
    o.y = is1 ? n.y : (is2 ? c.y : p.y);   // residue m+1
    o.z = is1 ? c.z : (is2 ? p.z : n.z);   // residue m+2
    o.w = is1 ? p.w : (is2 ? n.w : c.w);   // residue m
    return o;
}

__global__ __launch_bounds__(THREADS)
void ShiftLayer_66932770341347_kernel(const float* __restrict__ in,
                                      float* __restrict__ out) {
    const int warp = blockIdx.x * WARPS_PER_BLOCK + (threadIdx.x >> 5);
    const int lane = threadIdx.x & 31;

    const int g     = warp % GROUPS;                     // column group 0..2
    const int chunk = warp / GROUPS;
    const int chunks_per_b = L_DIM / T_R;                // 256
    const int b  = chunk / chunks_per_b;
    const int t0 = (chunk % chunks_per_b) * T_R;

    const size_t row0 = ((size_t)b * L_DIM + t0) * C_DIM + 4 * lane + 128 * g;
    const float* base  = in  + row0;
    float*       obase = out + row0;

    // Base channel residue: (4*lane + 128*g) % 3 == (lane + 2*g) % 3
    const int m = (lane + 2 * g) % 3;
    const bool is1 = (m == 1), is2 = (m == 2);

    const float4 z = make_float4(0.f, 0.f, 0.f, 0.f);

    // Prologue: prev = row t0-1 (zeros at sequence start), cur = row t0.
    float4 P = (t0 > 0) ? ldg4(base - C_DIM) : z;
    float4 C = ldg4(base);

    // Main: batches of 4 rows; all loads in a batch are independent (MLP=4).
    // Batches 0..6 cover rows 0..27; deepest load is row 28 (< T_R, in range).
    #pragma unroll
    for (int bi = 0; bi < (T_R / 4) - 1; ++bi) {
        const int r = 4 * bi;
        float4 N0 = ldg4(base + (size_t)(r + 1) * C_DIM);
        float4 N1 = ldg4(base + (size_t)(r + 2) * C_DIM);
        float4 N2 = ldg4(base + (size_t)(r + 3) * C_DIM);
        float4 N3 = ldg4(base + (size_t)(r + 4) * C_DIM);

        stg4(obase + (size_t)(r + 0) * C_DIM, route(P,  C,  N0, is1, is2));
        stg4(obase + (size_t)(r + 1) * C_DIM, route(C,  N0, N1, is1, is2));
        stg4(obase + (size_t)(r + 2) * C_DIM, route(N0, N1, N2, is1, is2));
        stg4(obase + (size_t)(r + 3) * C_DIM, route(N1, N2, N3, is1, is2));

        P = N2;
        C = N3;
    }

    // Epilogue: rows T_R-4 .. T_R-1; row t0+T_R may be past the sequence end.
    {
        const int r = T_R - 4;
        float4 N0 = ldg4(base + (size_t)(r + 1) * C_DIM);
        float4 N1 = ldg4(base + (size_t)(r + 2) * C_DIM);
        float4 N2 = ldg4(base + (size_t)(r + 3) * C_DIM);
        float4 N3 = (t0 + T_R < L_DIM) ? ldg4(base + (size_t)(r + 4) * C_DIM) : z;

        stg4(obase + (size_t)(r + 0) * C_DIM, route(P,  C,  N0, is1, is2));
        stg4(obase + (size_t)(r + 1) * C_DIM, route(C,  N0, N1, is1, is2));
        stg4(obase + (size_t)(r + 2) * C_DIM, route(N0, N1, N2, is1, is2));
        stg4(obase + (size_t)(r + 3) * C_DIM, route(N1, N2, N3, is1, is2));
    }
}

extern "C" void kernel_launch(void* const* d_in, const int* in_sizes, int n_in,
                              void* d_out, int out_size) {
    const float* mem = (const float*)d_in[0];
    float* out = (float*)d_out;
    (void)in_sizes; (void)n_in; (void)out_size;

    const int total_warps = B_DIM * (L_DIM / T_R) * GROUPS;   // 6144
    const int grid = total_warps / WARPS_PER_BLOCK;           // 1536 blocks
    ShiftLayer_66932770341347_kernel<<<grid, THREADS>>>(mem, out);
}

// round 5
// speedup vs baseline: 1.0077x; 1.0077x over previous
#include <cuda_runtime.h>
#include <cuda_bf16.h>

// ShiftLayer: out[b,t,c] = in[b, t+off[c], c], off[c] = {0,-1,+1} for c%3 = {0,1,2},
// zero padding at sequence ends. B=8, L=8192, C=384, fp32.
//
// Warp per (batch, 16-row chunk, 128-channel group); lane owns the float4 at
// channel 4*lane+128*g. Rows stream through registers with a depth-2 software
// pipeline: 2 independent LDG.128 issued before 2 STG.128 (MLP=2 inside the
// 32-reg / 64-warp occupancy envelope). All accesses are 512B-coalesced and
// use evict-first (.cs) policy — the stream has no L2 reuse.

#define B_DIM 8
#define L_DIM 8192
#define C_DIM 384
#define T_R   16                        // rows per warp chunk
#define GROUPS 3                        // 128-channel column groups
#define WARPS_PER_BLOCK 8
#define THREADS (WARPS_PER_BLOCK * 32)

__device__ __forceinline__ float4 ldg4(const float* p) {
    return __ldcs(reinterpret_cast<const float4*>(p));
}
__device__ __forceinline__ void stg4(float* p, float4 v) {
    __stcs(reinterpret_cast<float4*>(p), v);
}

// Component j of this lane's float4 has channel residue (m + j) % 3.
// residue 0 -> cur, 1 -> prev (out[t]=in[t-1]), 2 -> next (out[t]=in[t+1]).
__device__ __forceinline__ float4 route(float4 p, float4 c, float4 n,
                                        bool is1, bool is2) {
    float4 o;
    o.x = is1 ? p.x : (is2 ? n.x : c.x);   // residue m
    o.y = is1 ? n.y : (is2 ? c.y : p.y);   // residue m+1
    o.z = is1 ? c.z : (is2 ? p.z : n.z);   // residue m+2
    o.w = is1 ? p.w : (is2 ? n.w : c.w);   // residue m
    return o;
}

__global__ __launch_bounds__(THREADS)
void ShiftLayer_66932770341347_kernel(const float* __restrict__ in,
                                      float* __restrict__ out) {
    const int warp = blockIdx.x * WARPS_PER_BLOCK + (threadIdx.x >> 5);
    const int lane = threadIdx.x & 31;

    const int g     = warp % GROUPS;                     // column group 0..2
    const int chunk = warp / GROUPS;
    const int chunks_per_b = L_DIM / T_R;                // 512
    const int b  = chunk / chunks_per_b;
    const int t0 = (chunk % chunks_per_b) * T_R;

    const size_t row0 = ((size_t)b * L_DIM + t0) * C_DIM + 4 * lane + 128 * g;
    const float* base  = in  + row0;
    float*       obase = out + row0;

    // Base channel residue: (4*lane + 128*g) % 3 == (lane + 2*g) % 3
    const int m = (lane + 2 * g) % 3;
    const bool is1 = (m == 1), is2 = (m == 2);

    const float4 z = make_float4(0.f, 0.f, 0.f, 0.f);

    // Prologue: prev = row t0-1 (zeros at sequence start), cur = row t0.
    float4 P = (t0 > 0) ? ldg4(base - C_DIM) : z;
    float4 C = ldg4(base);

    // Main: 2 rows per iteration, both loads independent (MLP=2).
    // bi = 0..6 covers rows 0..13; deepest load is row 14 (< T_R, in range).
    #pragma unroll
    for (int bi = 0; bi < (T_R / 2) - 1; ++bi) {
        const int r = 2 * bi;
        float4 N1 = ldg4(base + (size_t)(r + 1) * C_DIM);
        float4 N2 = ldg4(base + (size_t)(r + 2) * C_DIM);

        stg4(obase + (size_t)(r + 0) * C_DIM, route(P, C,  N1, is1, is2));
        stg4(obase + (size_t)(r + 1) * C_DIM, route(C, N1, N2, is1, is2));

        P = N1;
        C = N2;
    }

    // Epilogue: rows T_R-2, T_R-1; row t0+T_R may be past the sequence end.
    {
        const int r = T_R - 2;
        float4 N1 = ldg4(base + (size_t)(r + 1) * C_DIM);
        float4 N2 = (t0 + T_R < L_DIM) ? ldg4(base + (size_t)(r + 2) * C_DIM) : z;

        stg4(obase + (size_t)(r + 0) * C_DIM, route(P, C,  N1, is1, is2));
        stg4(obase + (size_t)(r + 1) * C_DIM, route(C, N1, N2, is1, is2));
    }
}

extern "C" void kernel_launch(void* const* d_in, const int* in_sizes, int n_in,
                              void* d_out, int out_size) {
    const float* mem = (const float*)d_in[0];
    float* out = (float*)d_out;
    (void)in_sizes; (void)n_in; (void)out_size;

    const int total_warps = B_DIM * (L_DIM / T_R) * GROUPS;   // 12288
    const int grid = total_warps / WARPS_PER_BLOCK;           // 1536 blocks
    ShiftLayer_66932770341347_kernel<<<grid, THREADS>>>(mem, out);
}